// round 1
// baseline (speedup 1.0000x reference)
#include <cuda_runtime.h>
#include <cstdint>

#define NN 2048
#define FF 64
#define KTILE 256
#define NTILES (NN / KTILE)
#define RPB 64            // rows per block
#define THREADS 256
#define VREG 4360         // floats per q-region: 64 rows * 68 (64 f + 4 pad) + 8 skew
#define VSH_FLOATS (4 * VREG)            // 17440 floats
#define WSREG 66                          // float2 slots per q-region
#define WS_F2 (4 * WSREG)                 // 264 float2
#define SMEM_BYTES (VSH_FLOATS * 4 + WS_F2 * 8)   // 69760 + 2112 = 71872 B

// Precomputed {w1[n], sum_f v[n,f]^2}
__device__ float2 g_ws[NN];

__global__ void fm_prep(const float* __restrict__ w1, const float* __restrict__ v) {
    int n = blockIdx.x * blockDim.x + threadIdx.x;
    if (n >= NN) return;
    const float4* vr = (const float4*)(v + (size_t)n * FF);
    float s = 0.f;
#pragma unroll
    for (int i = 0; i < FF / 4; i++) {
        float4 t = vr[i];
        s += t.x * t.x + t.y * t.y + t.z * t.z + t.w * t.w;
    }
    g_ws[n] = make_float2(w1[n], s);
}

__device__ __forceinline__ void ffma2(unsigned long long& d,
                                      unsigned long long a,
                                      unsigned long long b) {
    // packed dual-fp32 FMA: d.lo += a.lo*b.lo, d.hi += a.hi*b.hi
    asm("fma.rn.f32x2 %0, %1, %2, %0;" : "+l"(d) : "l"(a), "l"(b));
}

__global__ void __launch_bounds__(THREADS, 2)
fm_main(const float* __restrict__ x, const float* __restrict__ w0p,
        const float* __restrict__ v, float* __restrict__ out) {
    extern __shared__ char smraw[];
    float*  vsh  = (float*)smraw;
    float2* wssh = (float2*)(smraw + VSH_FLOATS * sizeof(float));

    const int tid = threadIdx.x;
    const int q   = tid & 3;        // k-split quarter
    const int rl  = tid >> 2;       // local row
    const int row = blockIdx.x * RPB + rl;

    unsigned long long acc[32];     // 64 f-accumulators as f32x2 pairs
#pragma unroll
    for (int j = 0; j < 32; j++) acc[j] = 0ull;
    float sc = 0.f;                 // linear - 0.5 * x^2*s accumulator

    const float* xq = x + (size_t)row * NN + q * (KTILE / 4);

    for (int tile = 0; tile < NTILES; tile++) {
        __syncthreads();
        // cooperative v-tile load into per-q padded regions (row-major f within k-row)
        const float4* vg = (const float4*)(v + (size_t)tile * KTILE * FF);
#pragma unroll
        for (int j = 0; j < 16; j++) {
            int idx = j * THREADS + tid;   // float4 index 0..4095
            int kr  = idx >> 4;            // tile k-row 0..255
            int fi  = idx & 15;
            int qq  = kr >> 6, kl = kr & 63;
            *(float4*)&vsh[qq * VREG + kl * 68 + fi * 4] = vg[idx];
        }
        if (tid < KTILE) {
            int qq = tid >> 6, kl = tid & 63;
            wssh[qq * WSREG + kl] = g_ws[tile * KTILE + tid];
        }
        __syncthreads();

        const float*  xt = xq + tile * KTILE;
        const float*  vq = vsh + q * VREG;
        const float2* wq = wssh + q * WSREG;

        float4 xa = *(const float4*)(xt);
        float4 xb = *(const float4*)(xt + 4);
        for (int kk = 0; kk < 64; kk += 8) {
            float4 na, nb;
            if (kk < 56) {                       // double-buffer next 32B of x
                na = *(const float4*)(xt + kk + 8);
                nb = *(const float4*)(xt + kk + 12);
            }
            float xs[8] = {xa.x, xa.y, xa.z, xa.w, xb.x, xb.y, xb.z, xb.w};
#pragma unroll
            for (int u = 0; u < 8; u++) {
                float xv = xs[u];
                float2 wsk = wq[kk + u];
                sc = fmaf(xv, fmaf(-0.5f * xv, wsk.y, wsk.x), sc);
                unsigned int xi = __float_as_uint(xv);
                unsigned long long xx;
                asm("mov.b64 %0, {%1, %1};" : "=l"(xx) : "r"(xi));
                const ulonglong2* vrow = (const ulonglong2*)(vq + (kk + u) * 68);
#pragma unroll
                for (int fi = 0; fi < 16; fi++) {
                    ulonglong2 vv = vrow[fi];    // LDS.128: v[k][4f], conflict-free
                    ffma2(acc[2 * fi],     vv.x, xx);
                    ffma2(acc[2 * fi + 1], vv.y, xx);
                }
            }
            xa = na; xb = nb;
        }
    }

    // ---- epilogue: combine q-partials of xv through shared, then square-sum ----
    __syncthreads();
    float* part = vsh;              // [rl][f][q], row stride 260 (bank-skewed)
#pragma unroll
    for (int j = 0; j < 32; j++) {
        part[rl * 260 + (2 * j)     * 4 + q] = __uint_as_float((unsigned)(acc[j] & 0xffffffffull));
        part[rl * 260 + (2 * j + 1) * 4 + q] = __uint_as_float((unsigned)(acc[j] >> 32));
    }
    __syncthreads();
    float pw = 0.f;
#pragma unroll
    for (int i = 0; i < 16; i++) {
        int f = q * 16 + i;
        const float* p = &part[rl * 260 + f * 4];
        float xvf = (p[0] + p[1]) + (p[2] + p[3]);
        pw = fmaf(xvf, xvf, pw);
    }
    // reduce sc (k-ranges) and pw (f-chunks) across the 4 q-lanes
    sc += __shfl_xor_sync(0xffffffffu, sc, 1);
    sc += __shfl_xor_sync(0xffffffffu, sc, 2);
    pw += __shfl_xor_sync(0xffffffffu, pw, 1);
    pw += __shfl_xor_sync(0xffffffffu, pw, 2);
    if (q == 0) out[row] = w0p[0] + sc + 0.5f * pw;
}

extern "C" void kernel_launch(void* const* d_in, const int* in_sizes, int n_in,
                              void* d_out, int out_size) {
    const float* x  = (const float*)d_in[0];
    const float* w0 = (const float*)d_in[1];
    const float* w1 = (const float*)d_in[2];
    const float* v  = (const float*)d_in[3];
    float* out = (float*)d_out;
    int B = in_sizes[0] / NN;

    cudaFuncSetAttribute(fm_main, cudaFuncAttributeMaxDynamicSharedMemorySize, SMEM_BYTES);
    fm_prep<<<(NN + 255) / 256, 256>>>(w1, v);
    fm_main<<<B / RPB, THREADS, SMEM_BYTES>>>(x, w0, v, out);
}

// round 3
// speedup vs baseline: 1.5450x; 1.5450x over previous
#include <cuda_runtime.h>
#include <cstdint>

#define NN 2048
#define FF 64
#define KT 64
#define NT (NN / KT)
#define RPB 64
#define THREADS 256

typedef unsigned long long u64;

// Precomputed -0.5 * sum_f v[n,f]^2
__device__ float g_s[NN];

__global__ void fm_prep(const float* __restrict__ v) {
    int n = blockIdx.x * blockDim.x + threadIdx.x;
    if (n >= NN) return;
    const float4* vr = (const float4*)(v + (size_t)n * FF);
    float s = 0.f;
#pragma unroll
    for (int i = 0; i < FF / 4; i++) {
        float4 t = vr[i];
        s += t.x * t.x + t.y * t.y + t.z * t.z + t.w * t.w;
    }
    g_s[n] = -0.5f * s;
}

__device__ __forceinline__ void ffma2(u64& d, u64 a, u64 b) {
    asm("fma.rn.f32x2 %0, %1, %2, %0;" : "+l"(d) : "l"(a), "l"(b));
}
__device__ __forceinline__ u64 fma2(u64 a, u64 b, u64 c) {
    u64 d;
    asm("fma.rn.f32x2 %0, %1, %2, %3;" : "=l"(d) : "l"(a), "l"(b), "l"(c));
    return d;
}
__device__ __forceinline__ u64 bcast(float f) {
    u64 d; unsigned u = __float_as_uint(f);
    asm("mov.b64 %0, {%1, %1};" : "=l"(d) : "r"(u));
    return d;
}
__device__ __forceinline__ float2 unpk(u64 a) {
    float lo, hi;
    asm("mov.b64 {%0, %1}, %2;" : "=f"(lo), "=f"(hi) : "l"(a));
    return make_float2(lo, hi);
}

__global__ void __launch_bounds__(THREADS, 2)
fm_main(const float* __restrict__ x, const float* __restrict__ w0p,
        const float* __restrict__ w1, const float* __restrict__ v,
        float* __restrict__ out) {
    __shared__ float x_sh[RPB * 68];      // 64 rows, stride 68 (bank-skew)
    __shared__ float v_sh[KT * 64];       // chunk-permuted (see below)
    __shared__ float w1_sh[KT], s_sh[KT];

    const int tid = threadIdx.x;
    const int fg = tid & 7;               // f-group: owns f = 8*fg .. 8*fg+7
    const int rg = tid >> 3;              // row-group: owns rows rg, rg+32
    const int row0 = blockIdx.x * RPB;

    u64 acc[2][4];                        // [row j][f-pair]
    u64 lin2[2];                          // per-row linear+quad accumulator (f32x2 over k-pairs)
#pragma unroll
    for (int j = 0; j < 2; j++) {
        lin2[j] = 0ull;
#pragma unroll
        for (int p = 0; p < 4; p++) acc[j][p] = 0ull;
    }

    for (int tile = 0; tile < NT; tile++) {
        const int t0 = tile * KT;
        __syncthreads();
        // ---- cooperative x tile load: 64 rows x 64 k (stride 68) ----
#pragma unroll
        for (int it = 0; it < 4; it++) {
            int idx = it * THREADS + tid;          // float4 id 0..1023
            int r = idx >> 4, c = idx & 15;
            float4 t = *(const float4*)(x + (size_t)(row0 + r) * NN + t0 + 4 * c);
            *(float4*)&x_sh[r * 68 + 4 * c] = t;
        }
        // ---- cooperative v tile load with chunk permutation ----
        // chunk c (16B) of row k stored at word k*64 + 4*(c>>1) + 32*(c&1)
#pragma unroll
        for (int it = 0; it < 4; it++) {
            int idx = it * THREADS + tid;
            int k = idx >> 4, c = idx & 15;
            float4 t = *(const float4*)(v + (size_t)(t0 + k) * FF + 4 * c);
            *(float4*)&v_sh[k * 64 + 4 * (c >> 1) + 32 * (c & 1)] = t;
        }
        if (tid < 2 * KT) {
            int kl = tid & (KT - 1);
            if (tid < KT) w1_sh[kl] = w1[t0 + kl];
            else          s_sh[kl]  = g_s[t0 + kl];
        }
        __syncthreads();

        // ---- main GEMM part: 2 rows x 8 f per thread ----
        const float* xb0 = x_sh + rg * 68;
        const float* xb1 = x_sh + (rg + 32) * 68;
        const float* vb  = v_sh + 4 * fg;
#pragma unroll 4
        for (int kk = 0; kk < KT; kk += 4) {
            float4 x0 = *(const float4*)(xb0 + kk);
            float4 x1 = *(const float4*)(xb1 + kk);
            float xs0[4] = {x0.x, x0.y, x0.z, x0.w};
            float xs1[4] = {x1.x, x1.y, x1.z, x1.w};
#pragma unroll
            for (int i = 0; i < 4; i++) {
                const float* vr = vb + (kk + i) * 64;
                ulonglong2 va = *(const ulonglong2*)(vr);       // f = 8fg..8fg+3
                ulonglong2 vc = *(const ulonglong2*)(vr + 32);  // f = 8fg+4..8fg+7
                u64 xx0 = bcast(xs0[i]);
                u64 xx1 = bcast(xs1[i]);
                ffma2(acc[0][0], va.x, xx0);
                ffma2(acc[0][1], va.y, xx0);
                ffma2(acc[0][2], vc.x, xx0);
                ffma2(acc[0][3], vc.y, xx0);
                ffma2(acc[1][0], va.x, xx1);
                ffma2(acc[1][1], va.y, xx1);
                ffma2(acc[1][2], vc.x, xx1);
                ffma2(acc[1][3], vc.y, xx1);
            }
        }

        // ---- sc part: this thread handles k in [8*fg, 8*fg+8) for its 2 rows ----
        const float* wb = w1_sh + 8 * fg;
        const float* sb = s_sh + 8 * fg;
#pragma unroll
        for (int j = 0; j < 2; j++) {
            const float* xr = x_sh + (rg + 32 * j) * 68 + 8 * fg;
#pragma unroll
            for (int p = 0; p < 4; p++) {
                u64 xp = *(const u64*)(xr + 2 * p);
                // t = x * (-0.5*s) + w1  (s pre-negated & halved)
                u64 t = fma2(xp, *(const u64*)(sb + 2 * p), *(const u64*)(wb + 2 * p));
                ffma2(lin2[j], xp, t);
            }
        }
    }

    // ---- epilogue: square-sum accs, reduce over the 8 fg lanes ----
    const float w0v = w0p[0];
#pragma unroll
    for (int j = 0; j < 2; j++) {
        u64 sq = 0ull;
#pragma unroll
        for (int p = 0; p < 4; p++) ffma2(sq, acc[j][p], acc[j][p]);
        float2 s2 = unpk(sq);
        float pw = s2.x + s2.y;
        float2 l2 = unpk(lin2[j]);
        float sc = l2.x + l2.y;
        pw += __shfl_xor_sync(0xffffffffu, pw, 1);
        pw += __shfl_xor_sync(0xffffffffu, pw, 2);
        pw += __shfl_xor_sync(0xffffffffu, pw, 4);
        sc += __shfl_xor_sync(0xffffffffu, sc, 1);
        sc += __shfl_xor_sync(0xffffffffu, sc, 2);
        sc += __shfl_xor_sync(0xffffffffu, sc, 4);
        if (fg == 0) out[row0 + rg + 32 * j] = w0v + sc + 0.5f * pw;
    }
}

extern "C" void kernel_launch(void* const* d_in, const int* in_sizes, int n_in,
                              void* d_out, int out_size) {
    const float* x  = (const float*)d_in[0];
    const float* w0 = (const float*)d_in[1];
    const float* w1 = (const float*)d_in[2];
    const float* v  = (const float*)d_in[3];
    float* out = (float*)d_out;
    int B = in_sizes[0] / NN;

    fm_prep<<<(NN + 255) / 256, 256>>>(v);
    fm_main<<<B / RPB, THREADS>>>(x, w0, w1, v, out);
}

// round 14
// speedup vs baseline: 1.9079x; 1.2349x over previous
#include <cuda_runtime.h>
#include <cstdint>

#define NN 2048
#define FF 64
#define KT 64
#define NT (NN / KT)
#define RPB 64
#define THREADS 256
#define ST 68

typedef unsigned long long u64;

// Precomputed -0.5 * sum_f v[n,f]^2
__device__ float g_s[NN];

__global__ void fm_prep(const float* __restrict__ v) {
    int n = blockIdx.x * blockDim.x + threadIdx.x;
    if (n >= NN) return;
    const float4* vr = (const float4*)(v + (size_t)n * FF);
    float s = 0.f;
#pragma unroll
    for (int i = 0; i < FF / 4; i++) {
        float4 t = vr[i];
        s += t.x * t.x + t.y * t.y + t.z * t.z + t.w * t.w;
    }
    g_s[n] = -0.5f * s;
}

__device__ __forceinline__ void ffma2(u64& d, u64 a, u64 b) {
    asm("fma.rn.f32x2 %0, %1, %2, %0;" : "+l"(d) : "l"(a), "l"(b));
}
__device__ __forceinline__ u64 addx2(u64 a, u64 b) {
    u64 d;
    asm("add.rn.f32x2 %0, %1, %2;" : "=l"(d) : "l"(a), "l"(b));
    return d;
}
__device__ __forceinline__ u64 bcast(float f) {
    u64 d; unsigned u = __float_as_uint(f);
    asm("mov.b64 %0, {%1, %1};" : "=l"(d) : "r"(u));
    return d;
}
__device__ __forceinline__ float2 unpk(u64 a) {
    float lo, hi;
    asm("mov.b64 {%0, %1}, %2;" : "=f"(lo), "=f"(hi) : "l"(a));
    return make_float2(lo, hi);
}
__device__ __forceinline__ u64 shflx64(u64 v, int d) {
    unsigned lo = (unsigned)v, hi = (unsigned)(v >> 32);
    lo = __shfl_xor_sync(0xffffffffu, lo, d);
    hi = __shfl_xor_sync(0xffffffffu, hi, d);
    return (u64)lo | ((u64)hi << 32);
}

__global__ void __launch_bounds__(THREADS, 1)
fm_main(const float* __restrict__ x, const float* __restrict__ w0p,
        const float* __restrict__ w1, const float* __restrict__ v,
        float* __restrict__ out) {
    __shared__ __align__(16) float x_sh[KT * ST];   // [k][row], stride 68
    __shared__ __align__(16) float v_sh[KT * ST];   // [k][f],   stride 68
    __shared__ float w_sh[KT], s_sh[KT];

    const int tid = threadIdx.x;
    const int q   = tid & 7;            // k-interleave lane: k = kl*8 + q
    const int fg  = (tid >> 3) & 3;     // f-group: f = 16*fg .. 16*fg+15
    const int rg  = tid >> 5;           // row-group: rows 8*rg .. 8*rg+7
    const int pr  = tid & 63;           // prefetch row
    const int pcp = tid >> 6;           // prefetch col-pair base
    const int row0 = blockIdx.x * RPB;

    u64 acc[64];                        // [r][p]: 8 rows x 8 f-pairs
#pragma unroll
    for (int i = 0; i < 64; i++) acc[i] = 0ull;
    float scr[8];
#pragma unroll
    for (int r = 0; r < 8; r++) scr[r] = 0.f;

    float4 pfx[4], pfv[4];
    float pfws = 0.f;

    // ---- prefetch tile 0 ----
    {
        const int t0 = 0;
#pragma unroll
        for (int it = 0; it < 2; it++)
#pragma unroll
            for (int j = 0; j < 2; j++) {
                int cp = it * 4 + pcp;
                pfx[it * 2 + j] = *(const float4*)(x + (size_t)(row0 + pr) * NN + t0 + 8 * cp + 4 * j);
            }
#pragma unroll
        for (int it = 0; it < 4; it++) {
            int idx = it * THREADS + tid;
            int k = idx >> 4, c = idx & 15;
            pfv[it] = *(const float4*)(v + (size_t)(t0 + k) * FF + 4 * c);
        }
        if (tid < KT) pfws = w1[t0 + tid];
        else if (tid < 2 * KT) pfws = g_s[t0 + tid - KT];
    }

    for (int tile = 0; tile < NT; tile++) {
        // ---- store prefetched tile to smem ----
#pragma unroll
        for (int it = 0; it < 4; it++) {
            int idx = it * THREADS + tid;
            int k = idx >> 4, c = idx & 15;
            *(float4*)&v_sh[k * ST + 4 * c] = pfv[it];
        }
#pragma unroll
        for (int it = 0; it < 2; it++)
#pragma unroll
            for (int j = 0; j < 2; j++) {
                int c16 = 2 * (it * 4 + pcp) + j;
                float4 t = pfx[it * 2 + j];
                x_sh[(4 * c16 + 0) * ST + pr] = t.x;
                x_sh[(4 * c16 + 1) * ST + pr] = t.y;
                x_sh[(4 * c16 + 2) * ST + pr] = t.z;
                x_sh[(4 * c16 + 3) * ST + pr] = t.w;
            }
        if (tid < KT) w_sh[tid] = pfws;
        else if (tid < 2 * KT) s_sh[tid - KT] = pfws;
        __syncthreads();

        // ---- prefetch next tile (overlaps compute) ----
        if (tile + 1 < NT) {
            const int t0 = (tile + 1) * KT;
#pragma unroll
            for (int it = 0; it < 2; it++)
#pragma unroll
                for (int j = 0; j < 2; j++) {
                    int cp = it * 4 + pcp;
                    pfx[it * 2 + j] = *(const float4*)(x + (size_t)(row0 + pr) * NN + t0 + 8 * cp + 4 * j);
                }
#pragma unroll
            for (int it = 0; it < 4; it++) {
                int idx = it * THREADS + tid;
                int k = idx >> 4, c = idx & 15;
                pfv[it] = *(const float4*)(v + (size_t)(t0 + k) * FF + 4 * c);
            }
            if (tid < KT) pfws = w1[t0 + tid];
            else if (tid < 2 * KT) pfws = g_s[t0 + tid - KT];
        }

        // ---- main compute: 8 rows x 16 f per thread, k = kl*8 + q ----
#pragma unroll
        for (int kl = 0; kl < 8; kl++) {
            const int kw = kl * 8 + q;
            const float* xr = x_sh + kw * ST + 8 * rg;
            float4 xa = *(const float4*)(xr);
            float4 xb = *(const float4*)(xr + 4);
            const ulonglong2* vr = (const ulonglong2*)(v_sh + kw * ST + 16 * fg);
            ulonglong2 v0 = vr[0], v1 = vr[1], v2 = vr[2], v3 = vr[3];
            u64 vv[8] = {v0.x, v0.y, v1.x, v1.y, v2.x, v2.y, v3.x, v3.y};
            float xs[8] = {xa.x, xa.y, xa.z, xa.w, xb.x, xb.y, xb.z, xb.w};
#pragma unroll
            for (int r = 0; r < 8; r++) {
                u64 xx = bcast(xs[r]);
#pragma unroll
                for (int p = 0; p < 8; p++) ffma2(acc[r * 8 + p], vv[p], xx);
            }
        }

        // ---- linear/self term: this thread owns k for kl in {2fg, 2fg+1} ----
#pragma unroll
        for (int t = 0; t < 2; t++) {
            const int kw = (2 * fg + t) * 8 + q;
            const float wv = w_sh[kw], sv = s_sh[kw];
            const float* xr = x_sh + kw * ST + 8 * rg;
#pragma unroll
            for (int r = 0; r < 8; r++) {
                float xv = xr[r];
                scr[r] = fmaf(xv, fmaf(xv, sv, wv), scr[r]);
            }
        }
        __syncthreads();
    }

    // ---- epilogue ----
    // sum xv partials over the 8 q-lanes (lane bits 0..2)
#pragma unroll
    for (int d = 1; d <= 4; d <<= 1)
#pragma unroll
        for (int i = 0; i < 64; i++) acc[i] = addx2(acc[i], shflx64(acc[i], d));

    const float w0v = w0p[0];
#pragma unroll
    for (int r = 0; r < 8; r++) {
        u64 sq = 0ull;
#pragma unroll
        for (int p = 0; p < 8; p++) ffma2(sq, acc[r * 8 + p], acc[r * 8 + p]);
        float2 s2 = unpk(sq);
        float pw = s2.x + s2.y;
        // reduce over fg lanes (bits 3..4); q-lanes already identical
        pw += __shfl_xor_sync(0xffffffffu, pw, 8);
        pw += __shfl_xor_sync(0xffffffffu, pw, 16);
        // linear term owned disjointly by (q, fg): reduce over all 5 bits
        float sc = scr[r];
        sc += __shfl_xor_sync(0xffffffffu, sc, 1);
        sc += __shfl_xor_sync(0xffffffffu, sc, 2);
        sc += __shfl_xor_sync(0xffffffffu, sc, 4);
        sc += __shfl_xor_sync(0xffffffffu, sc, 8);
        sc += __shfl_xor_sync(0xffffffffu, sc, 16);
        if ((tid & 31) == r) out[row0 + 8 * rg + r] = w0v + sc + 0.5f * pw;
    }
}

extern "C" void kernel_launch(void* const* d_in, const int* in_sizes, int n_in,
                              void* d_out, int out_size) {
    const float* x  = (const float*)d_in[0];
    const float* w0 = (const float*)d_in[1];
    const float* w1 = (const float*)d_in[2];
    const float* v  = (const float*)d_in[3];
    float* out = (float*)d_out;
    int B = in_sizes[0] / NN;

    fm_prep<<<(NN + 255) / 256, 256>>>(v);
    fm_main<<<B / RPB, THREADS>>>(x, w0, w1, v, out);
}